// round 12
// baseline (speedup 1.0000x reference)
#include <cuda_runtime.h>
#include <cuda_fp16.h>
#include <cstdint>

static constexpr int NROWS = 16384;
static constexpr int DDIM  = 1024;

// ---------------- device scratch -----------------------------------------------
__device__ __half g_xh[(size_t)NROWS * DDIM];   // x fp16 [m][k]            (32 MB)
__device__ __half g_qt[(size_t)DDIM  * DDIM];   // Q^T fp16 [n][k]           (2 MB)

// ---------------- helpers ------------------------------------------------------
__device__ __forceinline__ uint32_t smem_u32(const void* p) {
    uint32_t a;
    asm("{ .reg .u64 t; cvta.to.shared.u64 t, %1; cvt.u32.u64 %0, t; }" : "=r"(a) : "l"(p));
    return a;
}

#define CP16(dst, src) \
    asm volatile("cp.async.cg.shared.global [%0], [%1], 16;" :: "r"(dst), "l"(src))
#define CP_COMMIT() asm volatile("cp.async.commit_group;")

#define LDSM4(r, addr) \
    asm volatile("ldmatrix.sync.aligned.m8n8.x4.shared.b16 {%0,%1,%2,%3}, [%4];" \
        : "=r"((r)[0]), "=r"((r)[1]), "=r"((r)[2]), "=r"((r)[3]) : "r"(addr))

#define MMA16816(d, a, b0, b1) \
    asm volatile("mma.sync.aligned.m16n8k16.row.col.f32.f16.f16.f32 " \
        "{%0,%1,%2,%3}, {%4,%5,%6,%7}, {%8,%9}, {%0,%1,%2,%3};" \
        : "+f"((d)[0]), "+f"((d)[1]), "+f"((d)[2]), "+f"((d)[3]) \
        : "r"((a)[0]), "r"((a)[1]), "r"((a)[2]), "r"((a)[3]), "r"(b0), "r"(b1))

// ---------------- pre-pass kernels ---------------------------------------------
__global__ void cvt_x_kernel(const float* __restrict__ x) {
    size_t i = ((size_t)blockIdx.x * blockDim.x + threadIdx.x) * 8;
    float4 a = *reinterpret_cast<const float4*>(x + i);
    float4 b = *reinterpret_cast<const float4*>(x + i + 4);
    __half2 h0 = __floats2half2_rn(a.x, a.y);
    __half2 h1 = __floats2half2_rn(a.z, a.w);
    __half2 h2 = __floats2half2_rn(b.x, b.y);
    __half2 h3 = __floats2half2_rn(b.z, b.w);
    uint4 v;
    v.x = *reinterpret_cast<uint32_t*>(&h0);
    v.y = *reinterpret_cast<uint32_t*>(&h1);
    v.z = *reinterpret_cast<uint32_t*>(&h2);
    v.w = *reinterpret_cast<uint32_t*>(&h3);
    *reinterpret_cast<uint4*>(&g_xh[i]) = v;
}

__global__ void cvt_qt_kernel(const float* __restrict__ Q) {
    __shared__ float t[32][33];
    int tx = threadIdx.x, ty = threadIdx.y;
    int bx = blockIdx.x * 32, by = blockIdx.y * 32;
    for (int i = 0; i < 4; i++)
        t[ty + i * 8][tx] = Q[(size_t)(by + ty + i * 8) * DDIM + bx + tx];
    __syncthreads();
    for (int i = 0; i < 4; i++)
        g_qt[(size_t)(bx + ty + i * 8) * DDIM + by + tx] = __float2half(t[tx][ty + i * 8]);
}

// ---------------- main fused GEMM + diag epilogue ------------------------------
// 512 threads (16 warps, 4M x 4N). Tile M=128, N=256, K=128. 2 cp.async stages.
// All-f16 stages, rows padded to 272B (odd multiple of 16 -> conflict-free ldmatrix).
static constexpr int TSTRIDE     = 272;                       // 256B data + 16B pad
static constexpr int STAGE_A     = 128 * TSTRIDE;             // 34816
static constexpr int STAGE_B     = 256 * TSTRIDE;             // 69632
static constexpr int STAGE_BYTES = STAGE_A + STAGE_B;         // 104448
static constexpr int BVEC_OFF    = 2 * STAGE_BYTES;           // 208896, 1024 floats
static constexpr int RED_OFF     = BVEC_OFF + 4096;           // 212992, 4x128 floats
static constexpr int SMEM_TOTAL  = RED_OFF + 2048;            // 215040

static constexpr int NITER = 32;                              // 4 n-passes x 8 k-tiles

__global__ void __launch_bounds__(512, 1) quad_mma_kernel(
    const float* __restrict__ x, const float* __restrict__ bv,
    const float* __restrict__ cv, float* __restrict__ out)
{
    extern __shared__ char smem[];
    const uint32_t sb = smem_u32(smem);
    const int tid  = threadIdx.x;
    const int lane = tid & 31;
    const int wid  = tid >> 5;
    const int mwarp = wid & 3;        // 32-row block within 128
    const int nwarp = wid >> 2;       // 64-col block within 256
    const int m0 = blockIdx.x * 128;

    float* bS  = reinterpret_cast<float*>(smem + BVEC_OFF);
    float* red = reinterpret_cast<float*>(smem + RED_OFF);
    for (int i = tid; i < 1024; i += 512) bS[i] = bv[i];

    const int rowoff = (lane & 7) + ((lane >> 3) & 1) * 8;  // ldmatrix row-in-16
    const int chsel  = lane >> 4;                           // ldmatrix 16B chunk

    // cp.async issue for iteration `it` (it = ntile*8 + ktile, K-tile = 128)
    auto issue = [&](int it) {
        const int nt = it >> 3, kt = it & 7;
        const int k0 = kt * 128, n0 = nt * 256;
        const uint32_t As = sb + (it & 1) * STAGE_BYTES;
        const uint32_t Bs = As + STAGE_A;
        #pragma unroll
        for (int r = 0; r < 4; r++) {   // A f16: 128 rows x 16 chunks = 2048
            const int idx = tid + r * 512;
            const int row = idx >> 4, ch = idx & 15;
            CP16(As + row * TSTRIDE + ch * 16,
                 (const void*)&g_xh[(size_t)(m0 + row) * DDIM + k0 + ch * 8]);
        }
        #pragma unroll
        for (int r = 0; r < 8; r++) {   // B f16: 256 rows x 16 chunks = 4096
            const int idx = tid + r * 512;
            const int row = idx >> 4, ch = idx & 15;
            CP16(Bs + row * TSTRIDE + ch * 16,
                 (const void*)&g_qt[(size_t)(n0 + row) * DDIM + k0 + ch * 8]);
        }
        CP_COMMIT();
    };

    issue(0);

    float rp[4] = {0.f, 0.f, 0.f, 0.f};
    float acc[2][8][4];

    for (int it = 0; it < NITER; it++) {
        const int kt = it & 7;
        if (kt == 0) {
            #pragma unroll
            for (int mb = 0; mb < 2; mb++)
                #pragma unroll
                for (int nb = 0; nb < 8; nb++)
                    #pragma unroll
                    for (int q = 0; q < 4; q++) acc[mb][nb][q] = 0.f;
        }

        // RACE-SAFE: wait for stage(it), barrier, then refill the other stage,
        // whose readers are all provably past the barrier.
        asm volatile("cp.async.wait_group 0;" ::: "memory");
        __syncthreads();
        if (it + 1 < NITER) issue(it + 1);

        const uint32_t As = sb + (it & 1) * STAGE_BYTES;
        const uint32_t Bs = As + STAGE_A;

        #pragma unroll
        for (int k16 = 0; k16 < 8; k16++) {
            uint32_t a[2][4];
            #pragma unroll
            for (int mb = 0; mb < 2; mb++)
                LDSM4(a[mb], As + (mwarp * 32 + mb * 16 + rowoff) * TSTRIDE
                                + (k16 * 2 + chsel) * 16);
            #pragma unroll
            for (int jh = 0; jh < 2; jh++) {
                uint32_t bf[2][4];
                #pragma unroll
                for (int jj = 0; jj < 2; jj++)
                    LDSM4(bf[jj], Bs + (nwarp * 64 + (jh * 2 + jj) * 16 + rowoff) * TSTRIDE
                                     + (k16 * 2 + chsel) * 16);
                #pragma unroll
                for (int mb = 0; mb < 2; mb++)
                    #pragma unroll
                    for (int jj = 0; jj < 2; jj++)
                        #pragma unroll
                        for (int h = 0; h < 2; h++)
                            MMA16816(acc[mb][(jh * 2 + jj) * 2 + h],
                                     a[mb], bf[jj][h], bf[jj][h + 2]);
            }
        }

        if (kt == 7) {
            // epilogue for this ntile: rp += (Z + b) .* x  (x read in fp32)
            const int n0 = (it >> 3) * 256;
            #pragma unroll
            for (int mb = 0; mb < 2; mb++) {
                const int r0 = m0 + mwarp * 32 + mb * 16 + (lane >> 2);
                #pragma unroll
                for (int nb = 0; nb < 8; nb++) {
                    const int n = n0 + nwarp * 64 + nb * 8 + 2 * (lane & 3);
                    float2 x0 = *reinterpret_cast<const float2*>(&x[(size_t)r0 * DDIM + n]);
                    float2 x1 = *reinterpret_cast<const float2*>(&x[(size_t)(r0 + 8) * DDIM + n]);
                    float2 bb = *reinterpret_cast<float2*>(&bS[n]);
                    rp[mb * 2 + 0] += (acc[mb][nb][0] + bb.x) * x0.x
                                    + (acc[mb][nb][1] + bb.y) * x0.y;
                    rp[mb * 2 + 1] += (acc[mb][nb][2] + bb.x) * x1.x
                                    + (acc[mb][nb][3] + bb.y) * x1.y;
                }
            }
        }
    }

    // ---- deterministic reduction: quad shfl (fixed order) -> smem -> fixed 4-way sum
    #pragma unroll
    for (int i = 0; i < 4; i++) {
        rp[i] += __shfl_xor_sync(0xFFFFFFFFu, rp[i], 1);
        rp[i] += __shfl_xor_sync(0xFFFFFFFFu, rp[i], 2);
    }
    __syncthreads();
    if ((lane & 3) == 0) {
        const int rbase = mwarp * 32 + (lane >> 2);
        red[nwarp * 128 + rbase +  0] = rp[0];
        red[nwarp * 128 + rbase +  8] = rp[1];
        red[nwarp * 128 + rbase + 16] = rp[2];
        red[nwarp * 128 + rbase + 24] = rp[3];
    }
    __syncthreads();
    if (tid < 128)
        out[m0 + tid] = ((red[tid] + red[128 + tid])
                       + (red[256 + tid] + red[384 + tid])) + cv[0];
}

// ---------------- launch -------------------------------------------------------
extern "C" void kernel_launch(void* const* d_in, const int* in_sizes, int n_in,
                              void* d_out, int out_size) {
    const float* x = (const float*)d_in[0];   // [16384, 1024]
    const float* Q = (const float*)d_in[1];   // [1024, 1024]
    const float* b = (const float*)d_in[2];   // [1024]
    const float* c = (const float*)d_in[3];   // [1]
    float* out = (float*)d_out;               // [16384, 1]

    cudaFuncSetAttribute(quad_mma_kernel,
                         cudaFuncAttributeMaxDynamicSharedMemorySize, SMEM_TOTAL);

    cvt_x_kernel<<<(NROWS * DDIM) / (256 * 8), 256>>>(x);
    cvt_qt_kernel<<<dim3(DDIM / 32, DDIM / 32), dim3(32, 8)>>>(Q);
    quad_mma_kernel<<<NROWS / 128, 512, SMEM_TOTAL>>>(x, b, c, out);
}